// round 11
// baseline (speedup 1.0000x reference)
#include <cuda_runtime.h>
#include <cstdint>

// ---------------------------------------------------------------------------
// SubsetOperator: output = one-hot(top_k(scores)) in fp32.
// Reference forward reduces exactly to this (non-selected lanes exactly 0.0f,
// selected 1.0f within ~2 ulp; top_k(khot)==top_k(scores), boundary margin
// ~6.5e-3 >> all perturbations).
//
// R10: two kernels.
//   kA : fused zero-fill (stcs streaming writes) + per-256-elem sub-max +
//        per-2048 segment max + per-block max. Reads use default caching so
//        scores stay L2-resident for kZ's candidate re-reads.
//   kZ : ONE block. T = exact k-th largest block-max via 4-pass radix select
//        (replaces the O(M^2) rank that cost ~8us); drill down
//        segmax -> submax -> elements; O(C^2) rank of ~50 candidates;
//        write 1.0f at top-k indices.
// ---------------------------------------------------------------------------

#define SEG_ELEMS    2048
#define SEG_F4       (SEG_ELEMS / 4)
#define SUB_F4       64                 // 256 elems per sub-segment
#define SUBS_PER_SEG 8
#define MAX_SEGS     8192
#define MAX_SUB      (MAX_SEGS * SUBS_PER_SEG)
#define MAX_BLKA     512
#define MAXK         1024
#define TPB_A        512
#define WARPS_A      (TPB_A / 32)
#define TPB_Z        1024
#define SEGL_CAP     1024
#define SUBL_CAP     2048
#define CKEY_CAP     2048

__device__ unsigned int g_seg_max[MAX_SEGS];
__device__ unsigned int g_sub_max[MAX_SUB];
__device__ unsigned int g_blk_max[MAX_BLKA];

// monotone mapping: fp32 total order -> uint32 order
__device__ __forceinline__ unsigned int fmono(float x) {
    unsigned int b = __float_as_uint(x);
    return b ^ ((unsigned int)((int)b >> 31) | 0x80000000u);
}

// ---------------------------------------------------------------------------
// kA: fused zero-fill + sub/seg/block maxima. Pure streaming pass.
// ---------------------------------------------------------------------------
__global__ void kA(const float* __restrict__ scores, float* __restrict__ out,
                   int n, int nSeg) {
    __shared__ unsigned int wmax[WARPS_A];
    int warp = threadIdx.x >> 5;
    int lane = threadIdx.x & 31;
    int seg  = blockIdx.x * WARPS_A + warp;

    unsigned int m = 0u;
    if (seg < nSeg) {
        const float4* s4 = (const float4*)scores;
        float4*       o4 = (float4*)out;
        int base4 = seg * SEG_F4;
        float4 z = make_float4(0.f, 0.f, 0.f, 0.f);
        unsigned int m2 = 0u;                    // running 256-elem max

#pragma unroll
        for (int j = 0; j < SEG_F4 / 32; ++j) {  // 16 iters, 128 elems each
            int idx4 = base4 + j * 32 + lane;
            int e0   = idx4 * 4;
            unsigned int c = 0u;
            if (e0 + 3 < n) {
                float4 v = s4[idx4];             // default caching: stay in L2
                __stcs(o4 + idx4, z);            // streaming zero write
                unsigned int u0 = fmono(v.x), u1 = fmono(v.y);
                unsigned int u2 = fmono(v.z), u3 = fmono(v.w);
                unsigned int a = u0 > u1 ? u0 : u1;
                unsigned int b = u2 > u3 ? u2 : u3;
                c = a > b ? a : b;
            } else {                              // generic tail
                for (int e = 0; e < 4; ++e) {
                    int i = e0 + e;
                    if (i < n) {
                        unsigned int uu = fmono(scores[i]);
                        if (uu > c) c = uu;
                        out[i] = 0.f;
                    }
                }
            }
            if (c > m2) m2 = c;
            if (j & 1) {                          // 256-elem boundary
                unsigned int t = m2;
#pragma unroll
                for (int off = 16; off > 0; off >>= 1) {
                    unsigned int o = __shfl_xor_sync(0xFFFFFFFFu, t, off);
                    if (o > t) t = o;
                }
                if (lane == 0) g_sub_max[seg * SUBS_PER_SEG + (j >> 1)] = t;
                if (t > m) m = t;                 // butterfly: all lanes have t
                m2 = 0u;
            }
        }
        if (lane == 0) g_seg_max[seg] = m;
    }
    if (lane == 0) wmax[warp] = m;
    __syncthreads();
    if (warp == 0) {
        unsigned int v = (lane < WARPS_A) ? wmax[lane] : 0u;
#pragma unroll
        for (int off = 8; off > 0; off >>= 1) {
            unsigned int o = __shfl_xor_sync(0xFFFFFFFFu, v, off);
            if (o > v) v = o;
        }
        if (lane == 0) g_blk_max[blockIdx.x] = v;
    }
}

// ---------------------------------------------------------------------------
// kZ: single block does everything after the pass.
// ---------------------------------------------------------------------------
__global__ void kZ(const float* __restrict__ scores, float* __restrict__ out,
                   const int* kptr, int n, int nSeg, int nBlkA) {
    __shared__ union {
        unsigned int       rankvals[MAX_SEGS];   // phase 1 (<=32 KB)
        unsigned long long ckeys[CKEY_CAP];      // phases 4-5 (16 KB)
    } u;
    __shared__ int seglist[SEGL_CAP];
    __shared__ int sublist[SUBL_CAP];
    __shared__ unsigned int hist[256];
    __shared__ unsigned int sscan[256];
    __shared__ unsigned int s_prefix;
    __shared__ int s_rem;
    __shared__ int s_nseg, s_nsub, s_nc;
    int tid = threadIdx.x;

    // ---- phase 1: T = exact k-th largest maximum via 4-pass radix select ----
    int k = kptr ? *kptr : 32;
    if (k < 1) k = 1;
    if (k > MAXK) k = MAXK;
    const unsigned int* src = (k <= nBlkA) ? g_blk_max : g_seg_max;
    int M = (k <= nBlkA) ? nBlkA : nSeg;
    if (k > M) k = M;

    if (tid == 0) {
        s_nseg = 0; s_nsub = 0; s_nc = 0;
        s_prefix = 0u; s_rem = k;
    }
    for (int j = tid; j < M; j += TPB_Z) u.rankvals[j] = src[j];
    __syncthreads();

    for (int pass = 3; pass >= 0; --pass) {
        int shift = pass * 8;
        unsigned int hs = (unsigned int)(shift + 8);
        if (tid < 256) hist[tid] = 0u;
        unsigned int pref = s_prefix;
        int rem = s_rem;
        __syncthreads();

        unsigned int prefHigh = (hs < 32u) ? (pref >> hs) : 0u;
        for (int j = tid; j < M; j += TPB_Z) {
            unsigned int v = u.rankvals[j];
            unsigned int vHigh = (hs < 32u) ? (v >> hs) : 0u;
            if (vHigh == prefHigh)
                atomicAdd(&hist[(v >> shift) & 255u], 1u);
        }
        __syncthreads();

        if (tid < 256) sscan[tid] = hist[tid];
        __syncthreads();
        // suffix scan over 256 bins (8 Hillis-Steele steps)
        for (int off = 1; off < 256; off <<= 1) {
            unsigned int add = 0u;
            if (tid < 256 && tid + off < 256) add = sscan[tid + off];
            __syncthreads();
            if (tid < 256) sscan[tid] += add;
            __syncthreads();
        }
        if (tid < 256) {
            unsigned int ge = sscan[tid];
            unsigned int gt = (tid < 255) ? sscan[tid + 1] : 0u;
            if ((int)gt < rem && (int)ge >= rem) {      // unique digit
                s_prefix = pref | (((unsigned int)tid) << shift);
                s_rem = rem - (int)gt;
            }
        }
        __syncthreads();
    }
    unsigned int T = s_prefix;    // exact k-th largest maximum

    // ---- phase 2: flag segments with segmax >= T (uint4 loads) ----
    int nSeg4 = nSeg >> 2;
    const uint4* sm4 = (const uint4*)g_seg_max;
    for (int j = tid; j < nSeg4; j += TPB_Z) {
        uint4 v = sm4[j];
        int b = 4 * j;
        if (v.x >= T) { int p = atomicAdd(&s_nseg, 1); if (p < SEGL_CAP) seglist[p] = b;     }
        if (v.y >= T) { int p = atomicAdd(&s_nseg, 1); if (p < SEGL_CAP) seglist[p] = b + 1; }
        if (v.z >= T) { int p = atomicAdd(&s_nseg, 1); if (p < SEGL_CAP) seglist[p] = b + 2; }
        if (v.w >= T) { int p = atomicAdd(&s_nseg, 1); if (p < SEGL_CAP) seglist[p] = b + 3; }
    }
    for (int j = nSeg4 * 4 + tid; j < nSeg; j += TPB_Z) {
        if (g_seg_max[j] >= T) {
            int p = atomicAdd(&s_nseg, 1);
            if (p < SEGL_CAP) seglist[p] = j;
        }
    }
    __syncthreads();
    int F = s_nseg < SEGL_CAP ? s_nseg : SEGL_CAP;

    // ---- phase 3: flag sub-segments with submax >= T ----
    for (int t = tid; t < F * SUBS_PER_SEG; t += TPB_Z) {
        int sub = seglist[t >> 3] * SUBS_PER_SEG + (t & 7);
        if (g_sub_max[sub] >= T) {
            int p = atomicAdd(&s_nsub, 1);
            if (p < SUBL_CAP) sublist[p] = sub;
        }
    }
    __syncthreads();
    int F2 = s_nsub < SUBL_CAP ? s_nsub : SUBL_CAP;

    // ---- phase 4: scan flagged sub-segments, collect candidates >= T ----
    // key = (u << 32) | ~idx : larger key = larger value, ties -> lower index
    const float4* s4 = (const float4*)scores;
    int W = F2 * SUB_F4;
    for (int w = tid; w < W; w += TPB_Z) {
        int idx4 = sublist[w >> 6] * SUB_F4 + (w & 63);
        int e0   = idx4 * 4;
        if (e0 + 3 < n) {
            float4 v = s4[idx4];
            unsigned int uu[4] = {fmono(v.x), fmono(v.y), fmono(v.z), fmono(v.w)};
#pragma unroll
            for (int e = 0; e < 4; ++e) {
                if (uu[e] >= T) {
                    int p = atomicAdd(&s_nc, 1);
                    if (p < CKEY_CAP)
                        u.ckeys[p] = ((unsigned long long)uu[e] << 32) |
                                     (unsigned int)(0xFFFFFFFFu - (unsigned int)(e0 + e));
                }
            }
        } else {
            for (int e = 0; e < 4; ++e) {
                int i = e0 + e;
                if (i < n) {
                    unsigned int uu = fmono(scores[i]);
                    if (uu >= T) {
                        int p = atomicAdd(&s_nc, 1);
                        if (p < CKEY_CAP)
                            u.ckeys[p] = ((unsigned long long)uu << 32) |
                                         (unsigned int)(0xFFFFFFFFu - (unsigned int)i);
                    }
                }
            }
        }
    }
    __syncthreads();
    int C = s_nc < CKEY_CAP ? s_nc : CKEY_CAP;

    // ---- phase 5: O(C^2) rank over unique keys, write 1.0f at top-k ----
    for (int j = tid; j < C; j += TPB_Z) {
        unsigned long long kj = u.ckeys[j];
        int rank = 0;
        for (int i = 0; i < C; ++i) rank += (u.ckeys[i] > kj);
        if (rank < k)
            out[0xFFFFFFFFu - (unsigned int)(kj & 0xFFFFFFFFu)] = 1.0f;
    }
}

// ---------------------------------------------------------------------------
extern "C" void kernel_launch(void* const* d_in, const int* in_sizes, int n_in,
                              void* d_out, int out_size) {
    const float* scores = (const float*)d_in[0];
    int n = in_sizes[0];
    const int* kptr = nullptr;
    for (int i = 0; i < n_in; ++i) {
        if (in_sizes[i] == 1) {
            kptr = (const int*)d_in[i];
        } else {
            scores = (const float*)d_in[i];
            n = in_sizes[i];
        }
    }
    float* out = (float*)d_out;

    int nSeg = (n + SEG_ELEMS - 1) / SEG_ELEMS;      // 8192 for N = 16,777,216
    if (nSeg > MAX_SEGS) nSeg = MAX_SEGS;
    int nBlkA = (nSeg + WARPS_A - 1) / WARPS_A;      // 512
    if (nBlkA > MAX_BLKA) nBlkA = MAX_BLKA;

    kA<<<nBlkA, TPB_A>>>(scores, out, n, nSeg);
    kZ<<<1, TPB_Z>>>(scores, out, kptr, n, nSeg, nBlkA);
}

// round 12
// speedup vs baseline: 1.2319x; 1.2319x over previous
#include <cuda_runtime.h>
#include <cstdint>

// ---------------------------------------------------------------------------
// SubsetOperator: output = one-hot(top_k(scores)) in fp32.
// Reference forward reduces exactly to this (non-selected lanes exactly 0.0f,
// selected 1.0f within ~2 ulp; top_k(khot)==top_k(scores), boundary margin
// ~6.5e-3 >> all perturbations).
//
// R11: two kernels.
//   kA : fused zero-fill + per-256-elem sub-max + per-2048 segment max +
//        per-block max. ldcs reads + stcs writes (R8 config: protects L2).
//   kZ : ONE block, 256 threads, ~12 cheap barriers.
//        T = top-16-bit floor of the k-th largest block-max via 2-pass radix
//        (histogram: smem atomics; suffix scan: warp-0 shuffles, no barriers).
//        Drill down segmax -> submax -> elements; O(C^2) rank of ~45
//        candidates; write 1.0f at top-k indices.
// ---------------------------------------------------------------------------

#define SEG_ELEMS    2048
#define SEG_F4       (SEG_ELEMS / 4)
#define SUB_F4       64                 // 256 elems per sub-segment
#define SUBS_PER_SEG 8
#define MAX_SEGS     8192
#define MAX_SUB      (MAX_SEGS * SUBS_PER_SEG)
#define MAX_BLKA     512
#define MAXK         1024
#define TPB_A        512
#define WARPS_A      (TPB_A / 32)
#define TPB_Z        256
#define SEGL_CAP     1024
#define SUBL_CAP     1536
#define CKEY_CAP     2048

__device__ unsigned int g_seg_max[MAX_SEGS];
__device__ unsigned int g_sub_max[MAX_SUB];
__device__ unsigned int g_blk_max[MAX_BLKA];

// monotone mapping: fp32 total order -> uint32 order
__device__ __forceinline__ unsigned int fmono(float x) {
    unsigned int b = __float_as_uint(x);
    return b ^ ((unsigned int)((int)b >> 31) | 0x80000000u);
}

// ---------------------------------------------------------------------------
// kA: fused zero-fill + sub/seg/block maxima. Pure streaming pass.
// ---------------------------------------------------------------------------
__global__ void kA(const float* __restrict__ scores, float* __restrict__ out,
                   int n, int nSeg) {
    __shared__ unsigned int wmax[WARPS_A];
    int warp = threadIdx.x >> 5;
    int lane = threadIdx.x & 31;
    int seg  = blockIdx.x * WARPS_A + warp;

    unsigned int m = 0u;
    if (seg < nSeg) {
        const float4* s4 = (const float4*)scores;
        float4*       o4 = (float4*)out;
        int base4 = seg * SEG_F4;
        float4 z = make_float4(0.f, 0.f, 0.f, 0.f);
        unsigned int m2 = 0u;                    // running 256-elem max

#pragma unroll
        for (int j = 0; j < SEG_F4 / 32; ++j) {  // 16 iters, 128 elems each
            int idx4 = base4 + j * 32 + lane;
            int e0   = idx4 * 4;
            unsigned int c = 0u;
            if (e0 + 3 < n) {
                float4 v = __ldcs(s4 + idx4);    // evict-first read
                __stcs(o4 + idx4, z);            // streaming zero write
                unsigned int u0 = fmono(v.x), u1 = fmono(v.y);
                unsigned int u2 = fmono(v.z), u3 = fmono(v.w);
                unsigned int a = u0 > u1 ? u0 : u1;
                unsigned int b = u2 > u3 ? u2 : u3;
                c = a > b ? a : b;
            } else {                              // generic tail
                for (int e = 0; e < 4; ++e) {
                    int i = e0 + e;
                    if (i < n) {
                        unsigned int uu = fmono(scores[i]);
                        if (uu > c) c = uu;
                        out[i] = 0.f;
                    }
                }
            }
            if (c > m2) m2 = c;
            if (j & 1) {                          // 256-elem boundary
                unsigned int t = m2;
#pragma unroll
                for (int off = 16; off > 0; off >>= 1) {
                    unsigned int o = __shfl_xor_sync(0xFFFFFFFFu, t, off);
                    if (o > t) t = o;
                }
                if (lane == 0) g_sub_max[seg * SUBS_PER_SEG + (j >> 1)] = t;
                if (t > m) m = t;                 // butterfly: all lanes have t
                m2 = 0u;
            }
        }
        if (lane == 0) g_seg_max[seg] = m;
    }
    if (lane == 0) wmax[warp] = m;
    __syncthreads();
    if (warp == 0) {
        unsigned int v = (lane < WARPS_A) ? wmax[lane] : 0u;
#pragma unroll
        for (int off = 8; off > 0; off >>= 1) {
            unsigned int o = __shfl_xor_sync(0xFFFFFFFFu, v, off);
            if (o > v) v = o;
        }
        if (lane == 0) g_blk_max[blockIdx.x] = v;
    }
}

// ---------------------------------------------------------------------------
// warp-0 radix step: suffix-scan 256 bins with shuffles, pick crossing digit.
// All lanes read s_prefix/s_rem before exactly one lane updates them.
// ---------------------------------------------------------------------------
__device__ __forceinline__ void radix_pick(const unsigned int* hist,
                                           unsigned int* s_prefix, int* s_rem,
                                           int shift, int lane) {
    unsigned int b[8];
    int base = lane * 8;                 // lane owns bins [base, base+8)
    unsigned int tot = 0u;
#pragma unroll
    for (int e = 0; e < 8; ++e) { b[e] = hist[base + e]; tot += b[e]; }
    unsigned int acc = tot;              // inclusive suffix over lanes
#pragma unroll
    for (int off = 1; off < 32; off <<= 1) {
        unsigned int o = __shfl_down_sync(0xFFFFFFFFu, acc, off);
        if (lane + off < 32) acc += o;
    }
    unsigned int run = acc - tot;        // count in bins of higher lanes
    int rem = *s_rem;
    unsigned int pref = *s_prefix;
#pragma unroll
    for (int e = 7; e >= 0; --e) {       // run == count of bins > (base+e)
        unsigned int ge = run + b[e];
        if ((int)run < rem && (int)ge >= rem) {   // unique crossing digit
            *s_prefix = pref | ((unsigned int)(base + e) << shift);
            *s_rem = rem - (int)run;
        }
        run = ge;
    }
}

// ---------------------------------------------------------------------------
// kZ: single block, 256 threads, does everything after the pass.
// ---------------------------------------------------------------------------
__global__ void kZ(const float* __restrict__ scores, float* __restrict__ out,
                   const int* kptr, int n, int nSeg, int nBlkA) {
    __shared__ unsigned int hist[256];
    __shared__ unsigned int s_prefix;
    __shared__ int s_rem;
    __shared__ int seglist[SEGL_CAP];
    __shared__ int sublist[SUBL_CAP];
    __shared__ unsigned long long ckeys[CKEY_CAP];
    __shared__ int s_nseg, s_nsub, s_nc;
    int tid  = threadIdx.x;
    int lane = tid & 31;

    // ---- phase 1: T = top-16-bit floor of k-th largest maximum ----
    int k = kptr ? *kptr : 32;
    if (k < 1) k = 1;
    if (k > MAXK) k = MAXK;
    const unsigned int* src = (k <= nBlkA) ? g_blk_max : g_seg_max;
    int M = (k <= nBlkA) ? nBlkA : nSeg;
    if (k > M) k = M;

    if (tid == 0) { s_prefix = 0u; s_rem = k; s_nseg = 0; s_nsub = 0; s_nc = 0; }
    hist[tid] = 0u;
    __syncthreads();

    // pass 1: bits 31..24
    for (int j = tid; j < M; j += TPB_Z) atomicAdd(&hist[src[j] >> 24], 1u);
    __syncthreads();
    if (tid < 32) radix_pick(hist, &s_prefix, &s_rem, 24, lane);
    __syncthreads();
    hist[tid] = 0u;
    unsigned int p8 = s_prefix >> 24;
    __syncthreads();

    // pass 2: bits 23..16, restricted to matching top byte
    for (int j = tid; j < M; j += TPB_Z) {
        unsigned int v = src[j];
        if ((v >> 24) == p8) atomicAdd(&hist[(v >> 16) & 255u], 1u);
    }
    __syncthreads();
    if (tid < 32) radix_pick(hist, &s_prefix, &s_rem, 16, lane);
    __syncthreads();

    unsigned int T = s_prefix;     // low 16 bits zero; T <= true k-th max
                                   // => #elements >= T is >= k (valid thresh)

    // ---- phase 2: flag segments with segmax >= T (uint4 loads) ----
    int nSeg4 = nSeg >> 2;
    const uint4* sm4 = (const uint4*)g_seg_max;
    for (int j = tid; j < nSeg4; j += TPB_Z) {
        uint4 v = sm4[j];
        int b = 4 * j;
        if (v.x >= T) { int p = atomicAdd(&s_nseg, 1); if (p < SEGL_CAP) seglist[p] = b;     }
        if (v.y >= T) { int p = atomicAdd(&s_nseg, 1); if (p < SEGL_CAP) seglist[p] = b + 1; }
        if (v.z >= T) { int p = atomicAdd(&s_nseg, 1); if (p < SEGL_CAP) seglist[p] = b + 2; }
        if (v.w >= T) { int p = atomicAdd(&s_nseg, 1); if (p < SEGL_CAP) seglist[p] = b + 3; }
    }
    for (int j = nSeg4 * 4 + tid; j < nSeg; j += TPB_Z) {
        if (g_seg_max[j] >= T) {
            int p = atomicAdd(&s_nseg, 1);
            if (p < SEGL_CAP) seglist[p] = j;
        }
    }
    __syncthreads();
    int F = s_nseg < SEGL_CAP ? s_nseg : SEGL_CAP;

    // ---- phase 3: flag sub-segments with submax >= T ----
    for (int t = tid; t < F * SUBS_PER_SEG; t += TPB_Z) {
        int sub = seglist[t >> 3] * SUBS_PER_SEG + (t & 7);
        if (g_sub_max[sub] >= T) {
            int p = atomicAdd(&s_nsub, 1);
            if (p < SUBL_CAP) sublist[p] = sub;
        }
    }
    __syncthreads();
    int F2 = s_nsub < SUBL_CAP ? s_nsub : SUBL_CAP;

    // ---- phase 4: scan flagged sub-segments, collect candidates >= T ----
    // key = (u << 32) | ~idx : larger key = larger value, ties -> lower index
    const float4* s4 = (const float4*)scores;
    int W = F2 * SUB_F4;
    for (int w = tid; w < W; w += TPB_Z) {
        int idx4 = sublist[w >> 6] * SUB_F4 + (w & 63);
        int e0   = idx4 * 4;
        if (e0 + 3 < n) {
            float4 v = s4[idx4];
            unsigned int uu[4] = {fmono(v.x), fmono(v.y), fmono(v.z), fmono(v.w)};
#pragma unroll
            for (int e = 0; e < 4; ++e) {
                if (uu[e] >= T) {
                    int p = atomicAdd(&s_nc, 1);
                    if (p < CKEY_CAP)
                        ckeys[p] = ((unsigned long long)uu[e] << 32) |
                                   (unsigned int)(0xFFFFFFFFu - (unsigned int)(e0 + e));
                }
            }
        } else {
            for (int e = 0; e < 4; ++e) {
                int i = e0 + e;
                if (i < n) {
                    unsigned int uu = fmono(scores[i]);
                    if (uu >= T) {
                        int p = atomicAdd(&s_nc, 1);
                        if (p < CKEY_CAP)
                            ckeys[p] = ((unsigned long long)uu << 32) |
                                       (unsigned int)(0xFFFFFFFFu - (unsigned int)i);
                    }
                }
            }
        }
    }
    __syncthreads();
    int C = s_nc < CKEY_CAP ? s_nc : CKEY_CAP;

    // ---- phase 5: O(C^2) rank over unique keys, write 1.0f at top-k ----
    for (int j = tid; j < C; j += TPB_Z) {
        unsigned long long kj = ckeys[j];
        int rank = 0;
        for (int i = 0; i < C; ++i) rank += (ckeys[i] > kj);
        if (rank < k)
            out[0xFFFFFFFFu - (unsigned int)(kj & 0xFFFFFFFFu)] = 1.0f;
    }
}

// ---------------------------------------------------------------------------
extern "C" void kernel_launch(void* const* d_in, const int* in_sizes, int n_in,
                              void* d_out, int out_size) {
    const float* scores = (const float*)d_in[0];
    int n = in_sizes[0];
    const int* kptr = nullptr;
    for (int i = 0; i < n_in; ++i) {
        if (in_sizes[i] == 1) {
            kptr = (const int*)d_in[i];
        } else {
            scores = (const float*)d_in[i];
            n = in_sizes[i];
        }
    }
    float* out = (float*)d_out;

    int nSeg = (n + SEG_ELEMS - 1) / SEG_ELEMS;      // 8192 for N = 16,777,216
    if (nSeg > MAX_SEGS) nSeg = MAX_SEGS;
    int nBlkA = (nSeg + WARPS_A - 1) / WARPS_A;      // 512
    if (nBlkA > MAX_BLKA) nBlkA = MAX_BLKA;

    kA<<<nBlkA, TPB_A>>>(scores, out, n, nSeg);
    kZ<<<1, TPB_Z>>>(scores, out, kptr, n, nSeg, nBlkA);
}

// round 13
// speedup vs baseline: 1.5832x; 1.2852x over previous
#include <cuda_runtime.h>
#include <cstdint>

// ---------------------------------------------------------------------------
// SubsetOperator: output = one-hot(top_k(scores)) in fp32.
// Reference forward reduces exactly to this (non-selected lanes exactly 0.0f,
// selected 1.0f within ~2 ulp; top_k(khot)==top_k(scores), boundary margin
// ~6.5e-3 >> all perturbations).
//
// R12: kA collects candidates >= T0 (fixed conservative threshold) inline
// during the streaming pass; kZ validates (C >= k proves candidates contain
// the top-k for ANY input) and just ranks ~180 keys. Full drill-down kept as
// fallback for inputs where the fast path doesn't certify.
// ---------------------------------------------------------------------------

#define SEG_ELEMS    2048
#define SEG_F4       (SEG_ELEMS / 4)
#define SUB_F4       64                 // 256 elems per sub-segment
#define SUBS_PER_SEG 8
#define MAX_SEGS     8192
#define MAX_SUB      (MAX_SEGS * SUBS_PER_SEG)
#define MAX_BLKA     512
#define MAXK         1024
#define TPB_A        512
#define WARPS_A      (TPB_A / 32)
#define TPB_Z        256
#define SEGL_CAP     1024
#define SUBL_CAP     1536
#define CKEY_CAP     2048
#define CAND_CAP     65536

__device__ unsigned int       g_seg_max[MAX_SEGS];
__device__ unsigned int       g_sub_max[MAX_SUB];
__device__ unsigned int       g_blk_max[MAX_BLKA];
__device__ unsigned long long g_cand[CAND_CAP];
__device__ int                g_cand_count;     // zero-init; kZ resets

// monotone mapping: fp32 total order -> uint32 order
__device__ __forceinline__ unsigned int fmono(float x) {
    unsigned int b = __float_as_uint(x);
    return b ^ ((unsigned int)((int)b >> 31) | 0x80000000u);
}

__device__ __forceinline__ void append_cand(unsigned int u, int idx) {
    int p = atomicAdd(&g_cand_count, 1);
    if (p < CAND_CAP)
        g_cand[p] = ((unsigned long long)u << 32) |
                    (unsigned int)(0xFFFFFFFFu - (unsigned int)idx);
}

// ---------------------------------------------------------------------------
// kA: fused zero-fill + sub/seg/block maxima + inline candidate collection.
// 8 float4 loads batched in registers per step for MLP.
// ---------------------------------------------------------------------------
__global__ void __launch_bounds__(TPB_A)
kA(const float* __restrict__ scores, float* __restrict__ out,
   int n, int nSeg) {
    __shared__ unsigned int wmax[WARPS_A];
    int warp = threadIdx.x >> 5;
    int lane = threadIdx.x & 31;
    int seg  = blockIdx.x * WARPS_A + warp;
    const unsigned int T0 = fmono(4.3f);     // conservative candidate floor

    unsigned int m = 0u;
    if (seg < nSeg) {
        const float4* s4 = (const float4*)scores;
        float4*       o4 = (float4*)out;
        int base4 = seg * SEG_F4;
        float4 z = make_float4(0.f, 0.f, 0.f, 0.f);
        bool full = (base4 + SEG_F4) * 4 <= n;

        if (full) {
#pragma unroll
            for (int h = 0; h < 2; ++h) {              // 2 halves x 8 float4
                int b4 = base4 + h * 256;              // 8 * 32
                float4 v[8];
#pragma unroll
                for (int j = 0; j < 8; ++j)            // batched loads: MLP=8
                    v[j] = __ldcs(s4 + b4 + j * 32 + lane);
#pragma unroll
                for (int j = 0; j < 8; ++j)
                    __stcs(o4 + b4 + j * 32 + lane, z);
#pragma unroll
                for (int j = 0; j < 8; j += 2) {       // 256-elem sub-segment
                    unsigned int u0 = fmono(v[j].x),   u1 = fmono(v[j].y);
                    unsigned int u2 = fmono(v[j].z),   u3 = fmono(v[j].w);
                    unsigned int u4 = fmono(v[j+1].x), u5 = fmono(v[j+1].y);
                    unsigned int u6 = fmono(v[j+1].z), u7 = fmono(v[j+1].w);
                    unsigned int a = u0 > u1 ? u0 : u1;
                    unsigned int b = u2 > u3 ? u2 : u3;
                    unsigned int d = u4 > u5 ? u4 : u5;
                    unsigned int e = u6 > u7 ? u6 : u7;
                    unsigned int ab = a > b ? a : b;
                    unsigned int de = d > e ? d : e;
                    unsigned int c  = ab > de ? ab : de;
                    if (c >= T0) {                     // rare: append cands
                        int i0 = (b4 + j * 32 + lane) * 4;
                        int i1 = (b4 + (j + 1) * 32 + lane) * 4;
                        if (u0 >= T0) append_cand(u0, i0);
                        if (u1 >= T0) append_cand(u1, i0 + 1);
                        if (u2 >= T0) append_cand(u2, i0 + 2);
                        if (u3 >= T0) append_cand(u3, i0 + 3);
                        if (u4 >= T0) append_cand(u4, i1);
                        if (u5 >= T0) append_cand(u5, i1 + 1);
                        if (u6 >= T0) append_cand(u6, i1 + 2);
                        if (u7 >= T0) append_cand(u7, i1 + 3);
                    }
                    unsigned int t = c;                // warp submax reduce
#pragma unroll
                    for (int off = 16; off > 0; off >>= 1) {
                        unsigned int o = __shfl_xor_sync(0xFFFFFFFFu, t, off);
                        if (o > t) t = o;
                    }
                    if (lane == 0)
                        g_sub_max[seg * SUBS_PER_SEG + h * 4 + (j >> 1)] = t;
                    if (t > m) m = t;
                }
            }
        } else {                                       // generic tail segment
            unsigned int m2 = 0u;
            for (int j = 0; j < SEG_F4 / 32; ++j) {
                int idx4 = base4 + j * 32 + lane;
                unsigned int c = 0u;
                for (int e = 0; e < 4; ++e) {
                    int i = idx4 * 4 + e;
                    if (i < n) {
                        unsigned int uu = fmono(scores[i]);
                        if (uu > c) c = uu;
                        if (uu >= T0) append_cand(uu, i);
                        out[i] = 0.f;
                    }
                }
                if (c > m2) m2 = c;
                if (j & 1) {
                    unsigned int t = m2;
                    for (int off = 16; off > 0; off >>= 1) {
                        unsigned int o = __shfl_xor_sync(0xFFFFFFFFu, t, off);
                        if (o > t) t = o;
                    }
                    if (lane == 0)
                        g_sub_max[seg * SUBS_PER_SEG + (j >> 1)] = t;
                    if (t > m) m = t;
                    m2 = 0u;
                }
            }
        }
        if (lane == 0) g_seg_max[seg] = m;
    }
    if (lane == 0) wmax[warp] = m;
    __syncthreads();
    if (warp == 0) {
        unsigned int v = (lane < WARPS_A) ? wmax[lane] : 0u;
#pragma unroll
        for (int off = 8; off > 0; off >>= 1) {
            unsigned int o = __shfl_xor_sync(0xFFFFFFFFu, v, off);
            if (o > v) v = o;
        }
        if (lane == 0) g_blk_max[blockIdx.x] = v;
    }
}

// ---------------------------------------------------------------------------
// warp-0 radix step for the fallback path.
// ---------------------------------------------------------------------------
__device__ __forceinline__ void radix_pick(const unsigned int* hist,
                                           unsigned int* s_prefix, int* s_rem,
                                           int shift, int lane) {
    unsigned int b[8];
    int base = lane * 8;
    unsigned int tot = 0u;
#pragma unroll
    for (int e = 0; e < 8; ++e) { b[e] = hist[base + e]; tot += b[e]; }
    unsigned int acc = tot;
#pragma unroll
    for (int off = 1; off < 32; off <<= 1) {
        unsigned int o = __shfl_down_sync(0xFFFFFFFFu, acc, off);
        if (lane + off < 32) acc += o;
    }
    unsigned int run = acc - tot;
    int rem = *s_rem;
    unsigned int pref = *s_prefix;
#pragma unroll
    for (int e = 7; e >= 0; --e) {
        unsigned int ge = run + b[e];
        if ((int)run < rem && (int)ge >= rem) {
            *s_prefix = pref | ((unsigned int)(base + e) << shift);
            *s_rem = rem - (int)run;
        }
        run = ge;
    }
}

// ---------------------------------------------------------------------------
// kZ: single block. Fast path: rank precollected candidates (valid whenever
// C >= k, which proves candidates contain the top-k). Else full drill-down.
// ---------------------------------------------------------------------------
__global__ void kZ(const float* __restrict__ scores, float* __restrict__ out,
                   const int* kptr, int n, int nSeg, int nBlkA) {
    __shared__ unsigned long long ckeys[CKEY_CAP];
    __shared__ unsigned int hist[256];
    __shared__ unsigned int s_prefix;
    __shared__ int s_rem;
    __shared__ int seglist[SEGL_CAP];
    __shared__ int sublist[SUBL_CAP];
    __shared__ int s_nseg, s_nsub, s_nc;
    int tid  = threadIdx.x;
    int lane = tid & 31;

    int k = kptr ? *kptr : 32;
    if (k < 1) k = 1;
    if (k > MAXK) k = MAXK;

    int C0 = g_cand_count;

    if (C0 >= k && C0 <= CKEY_CAP) {
        // ---- FAST PATH: candidates provably contain the top-k ----
        for (int j = tid; j < C0; j += TPB_Z) ckeys[j] = g_cand[j];
        __syncthreads();
        for (int j = tid; j < C0; j += TPB_Z) {
            unsigned long long kj = ckeys[j];
            int rank = 0;
            for (int i = 0; i < C0; ++i) rank += (ckeys[i] > kj);
            if (rank < k)
                out[0xFFFFFFFFu - (unsigned int)(kj & 0xFFFFFFFFu)] = 1.0f;
        }
        __syncthreads();
        if (tid == 0) g_cand_count = 0;      // reset for next replay
        return;
    }

    // ---- FALLBACK: full drill-down (any input shape) ----
    const unsigned int* src = (k <= nBlkA) ? g_blk_max : g_seg_max;
    int M = (k <= nBlkA) ? nBlkA : nSeg;
    if (k > M) k = M;

    if (tid == 0) { s_prefix = 0u; s_rem = k; s_nseg = 0; s_nsub = 0; s_nc = 0; }
    hist[tid] = 0u;
    __syncthreads();

    for (int j = tid; j < M; j += TPB_Z) atomicAdd(&hist[src[j] >> 24], 1u);
    __syncthreads();
    if (tid < 32) radix_pick(hist, &s_prefix, &s_rem, 24, lane);
    __syncthreads();
    hist[tid] = 0u;
    unsigned int p8 = s_prefix >> 24;
    __syncthreads();
    for (int j = tid; j < M; j += TPB_Z) {
        unsigned int v = src[j];
        if ((v >> 24) == p8) atomicAdd(&hist[(v >> 16) & 255u], 1u);
    }
    __syncthreads();
    if (tid < 32) radix_pick(hist, &s_prefix, &s_rem, 16, lane);
    __syncthreads();
    unsigned int T = s_prefix;     // 16-bit floor <= true k-th max

    int nSeg4 = nSeg >> 2;
    const uint4* sm4 = (const uint4*)g_seg_max;
    for (int j = tid; j < nSeg4; j += TPB_Z) {
        uint4 v = sm4[j];
        int b = 4 * j;
        if (v.x >= T) { int p = atomicAdd(&s_nseg, 1); if (p < SEGL_CAP) seglist[p] = b;     }
        if (v.y >= T) { int p = atomicAdd(&s_nseg, 1); if (p < SEGL_CAP) seglist[p] = b + 1; }
        if (v.z >= T) { int p = atomicAdd(&s_nseg, 1); if (p < SEGL_CAP) seglist[p] = b + 2; }
        if (v.w >= T) { int p = atomicAdd(&s_nseg, 1); if (p < SEGL_CAP) seglist[p] = b + 3; }
    }
    for (int j = nSeg4 * 4 + tid; j < nSeg; j += TPB_Z) {
        if (g_seg_max[j] >= T) {
            int p = atomicAdd(&s_nseg, 1);
            if (p < SEGL_CAP) seglist[p] = j;
        }
    }
    __syncthreads();
    int F = s_nseg < SEGL_CAP ? s_nseg : SEGL_CAP;

    for (int t = tid; t < F * SUBS_PER_SEG; t += TPB_Z) {
        int sub = seglist[t >> 3] * SUBS_PER_SEG + (t & 7);
        if (g_sub_max[sub] >= T) {
            int p = atomicAdd(&s_nsub, 1);
            if (p < SUBL_CAP) sublist[p] = sub;
        }
    }
    __syncthreads();
    int F2 = s_nsub < SUBL_CAP ? s_nsub : SUBL_CAP;

    const float4* s4 = (const float4*)scores;
    int W = F2 * SUB_F4;
    for (int w = tid; w < W; w += TPB_Z) {
        int idx4 = sublist[w >> 6] * SUB_F4 + (w & 63);
        int e0   = idx4 * 4;
        if (e0 + 3 < n) {
            float4 v = s4[idx4];
            unsigned int uu[4] = {fmono(v.x), fmono(v.y), fmono(v.z), fmono(v.w)};
#pragma unroll
            for (int e = 0; e < 4; ++e) {
                if (uu[e] >= T) {
                    int p = atomicAdd(&s_nc, 1);
                    if (p < CKEY_CAP)
                        ckeys[p] = ((unsigned long long)uu[e] << 32) |
                                   (unsigned int)(0xFFFFFFFFu - (unsigned int)(e0 + e));
                }
            }
        } else {
            for (int e = 0; e < 4; ++e) {
                int i = e0 + e;
                if (i < n) {
                    unsigned int uu = fmono(scores[i]);
                    if (uu >= T) {
                        int p = atomicAdd(&s_nc, 1);
                        if (p < CKEY_CAP)
                            ckeys[p] = ((unsigned long long)uu << 32) |
                                       (unsigned int)(0xFFFFFFFFu - (unsigned int)i);
                    }
                }
            }
        }
    }
    __syncthreads();
    int C = s_nc < CKEY_CAP ? s_nc : CKEY_CAP;

    for (int j = tid; j < C; j += TPB_Z) {
        unsigned long long kj = ckeys[j];
        int rank = 0;
        for (int i = 0; i < C; ++i) rank += (ckeys[i] > kj);
        if (rank < k)
            out[0xFFFFFFFFu - (unsigned int)(kj & 0xFFFFFFFFu)] = 1.0f;
    }
    __syncthreads();
    if (tid == 0) g_cand_count = 0;          // reset for next replay
}

// ---------------------------------------------------------------------------
extern "C" void kernel_launch(void* const* d_in, const int* in_sizes, int n_in,
                              void* d_out, int out_size) {
    const float* scores = (const float*)d_in[0];
    int n = in_sizes[0];
    const int* kptr = nullptr;
    for (int i = 0; i < n_in; ++i) {
        if (in_sizes[i] == 1) {
            kptr = (const int*)d_in[i];
        } else {
            scores = (const float*)d_in[i];
            n = in_sizes[i];
        }
    }
    float* out = (float*)d_out;

    int nSeg = (n + SEG_ELEMS - 1) / SEG_ELEMS;      // 8192 for N = 16,777,216
    if (nSeg > MAX_SEGS) nSeg = MAX_SEGS;
    int nBlkA = (nSeg + WARPS_A - 1) / WARPS_A;      // 512
    if (nBlkA > MAX_BLKA) nBlkA = MAX_BLKA;

    kA<<<nBlkA, TPB_A>>>(scores, out, n, nSeg);
    kZ<<<1, TPB_Z>>>(scores, out, kptr, n, nSeg, nBlkA);
}

// round 15
// speedup vs baseline: 1.6038x; 1.0130x over previous
#include <cuda_runtime.h>
#include <cstdint>

// ---------------------------------------------------------------------------
// SubsetOperator: output = one-hot(top_k(scores)) in fp32.
// Reference forward reduces exactly to this (non-selected lanes exactly 0.0f,
// selected 1.0f within ~2 ulp; top_k(khot)==top_k(scores), boundary margin
// ~6.5e-3 >> all perturbations).
//
// R13: R12 + PDL. kZ is launched with programmatic stream serialization and
// begins its launch/ramp/prologue while kA is still streaming; kA triggers
// launch_dependents as its last instruction; kZ griddepcontrol.wait's before
// reading kA's results. Falls back to plain serialization if PDL is inert.
// ---------------------------------------------------------------------------

#define SEG_ELEMS    2048
#define SEG_F4       (SEG_ELEMS / 4)
#define SUB_F4       64                 // 256 elems per sub-segment
#define SUBS_PER_SEG 8
#define MAX_SEGS     8192
#define MAX_SUB      (MAX_SEGS * SUBS_PER_SEG)
#define MAX_BLKA     512
#define MAXK         1024
#define TPB_A        512
#define WARPS_A      (TPB_A / 32)
#define TPB_Z        256
#define SEGL_CAP     1024
#define SUBL_CAP     1536
#define CKEY_CAP     2048
#define CAND_CAP     65536

__device__ unsigned int       g_seg_max[MAX_SEGS];
__device__ unsigned int       g_sub_max[MAX_SUB];
__device__ unsigned int       g_blk_max[MAX_BLKA];
__device__ unsigned long long g_cand[CAND_CAP];
__device__ int                g_cand_count;     // zero-init; kZ resets

// monotone mapping: fp32 total order -> uint32 order
__device__ __forceinline__ unsigned int fmono(float x) {
    unsigned int b = __float_as_uint(x);
    return b ^ ((unsigned int)((int)b >> 31) | 0x80000000u);
}

__device__ __forceinline__ void append_cand(unsigned int u, int idx) {
    int p = atomicAdd(&g_cand_count, 1);
    if (p < CAND_CAP)
        g_cand[p] = ((unsigned long long)u << 32) |
                    (unsigned int)(0xFFFFFFFFu - (unsigned int)idx);
}

// ---------------------------------------------------------------------------
// kA: fused zero-fill + sub/seg/block maxima + inline candidate collection.
// ---------------------------------------------------------------------------
__global__ void __launch_bounds__(TPB_A)
kA(const float* __restrict__ scores, float* __restrict__ out,
   int n, int nSeg) {
    __shared__ unsigned int wmax[WARPS_A];
    int warp = threadIdx.x >> 5;
    int lane = threadIdx.x & 31;
    int seg  = blockIdx.x * WARPS_A + warp;
    const unsigned int T0 = fmono(4.3f);     // conservative candidate floor

    unsigned int m = 0u;
    if (seg < nSeg) {
        const float4* s4 = (const float4*)scores;
        float4*       o4 = (float4*)out;
        int base4 = seg * SEG_F4;
        float4 z = make_float4(0.f, 0.f, 0.f, 0.f);
        bool full = (base4 + SEG_F4) * 4 <= n;

        if (full) {
#pragma unroll
            for (int h = 0; h < 2; ++h) {              // 2 halves x 8 float4
                int b4 = base4 + h * 256;              // 8 * 32
                float4 v[8];
#pragma unroll
                for (int j = 0; j < 8; ++j)            // batched loads: MLP=8
                    v[j] = __ldcs(s4 + b4 + j * 32 + lane);
#pragma unroll
                for (int j = 0; j < 8; ++j)
                    __stcs(o4 + b4 + j * 32 + lane, z);
#pragma unroll
                for (int j = 0; j < 8; j += 2) {       // 256-elem sub-segment
                    unsigned int u0 = fmono(v[j].x),   u1 = fmono(v[j].y);
                    unsigned int u2 = fmono(v[j].z),   u3 = fmono(v[j].w);
                    unsigned int u4 = fmono(v[j+1].x), u5 = fmono(v[j+1].y);
                    unsigned int u6 = fmono(v[j+1].z), u7 = fmono(v[j+1].w);
                    unsigned int a = u0 > u1 ? u0 : u1;
                    unsigned int b = u2 > u3 ? u2 : u3;
                    unsigned int d = u4 > u5 ? u4 : u5;
                    unsigned int e = u6 > u7 ? u6 : u7;
                    unsigned int ab = a > b ? a : b;
                    unsigned int de = d > e ? d : e;
                    unsigned int c  = ab > de ? ab : de;
                    if (c >= T0) {                     // rare: append cands
                        int i0 = (b4 + j * 32 + lane) * 4;
                        int i1 = (b4 + (j + 1) * 32 + lane) * 4;
                        if (u0 >= T0) append_cand(u0, i0);
                        if (u1 >= T0) append_cand(u1, i0 + 1);
                        if (u2 >= T0) append_cand(u2, i0 + 2);
                        if (u3 >= T0) append_cand(u3, i0 + 3);
                        if (u4 >= T0) append_cand(u4, i1);
                        if (u5 >= T0) append_cand(u5, i1 + 1);
                        if (u6 >= T0) append_cand(u6, i1 + 2);
                        if (u7 >= T0) append_cand(u7, i1 + 3);
                    }
                    unsigned int t = c;                // warp submax reduce
#pragma unroll
                    for (int off = 16; off > 0; off >>= 1) {
                        unsigned int o = __shfl_xor_sync(0xFFFFFFFFu, t, off);
                        if (o > t) t = o;
                    }
                    if (lane == 0)
                        g_sub_max[seg * SUBS_PER_SEG + h * 4 + (j >> 1)] = t;
                    if (t > m) m = t;
                }
            }
        } else {                                       // generic tail segment
            unsigned int m2 = 0u;
            for (int j = 0; j < SEG_F4 / 32; ++j) {
                int idx4 = base4 + j * 32 + lane;
                unsigned int c = 0u;
                for (int e = 0; e < 4; ++e) {
                    int i = idx4 * 4 + e;
                    if (i < n) {
                        unsigned int uu = fmono(scores[i]);
                        if (uu > c) c = uu;
                        if (uu >= T0) append_cand(uu, i);
                        out[i] = 0.f;
                    }
                }
                if (c > m2) m2 = c;
                if (j & 1) {
                    unsigned int t = m2;
                    for (int off = 16; off > 0; off >>= 1) {
                        unsigned int o = __shfl_xor_sync(0xFFFFFFFFu, t, off);
                        if (o > t) t = o;
                    }
                    if (lane == 0)
                        g_sub_max[seg * SUBS_PER_SEG + (j >> 1)] = t;
                    if (t > m) m = t;
                    m2 = 0u;
                }
            }
        }
        if (lane == 0) g_seg_max[seg] = m;
    }
    if (lane == 0) wmax[warp] = m;
    __syncthreads();
    if (warp == 0) {
        unsigned int v = (lane < WARPS_A) ? wmax[lane] : 0u;
#pragma unroll
        for (int off = 8; off > 0; off >>= 1) {
            unsigned int o = __shfl_xor_sync(0xFFFFFFFFu, v, off);
            if (o > v) v = o;
        }
        if (lane == 0) g_blk_max[blockIdx.x] = v;
    }
    // PDL: all of this block's global writes are done -> allow dependent
    // grid to launch. (Fires once every block has executed it.)
    asm volatile("griddepcontrol.launch_dependents;");
}

// ---------------------------------------------------------------------------
// warp-0 radix step for the fallback path.
// ---------------------------------------------------------------------------
__device__ __forceinline__ void radix_pick(const unsigned int* hist,
                                           unsigned int* s_prefix, int* s_rem,
                                           int shift, int lane) {
    unsigned int b[8];
    int base = lane * 8;
    unsigned int tot = 0u;
#pragma unroll
    for (int e = 0; e < 8; ++e) { b[e] = hist[base + e]; tot += b[e]; }
    unsigned int acc = tot;
#pragma unroll
    for (int off = 1; off < 32; off <<= 1) {
        unsigned int o = __shfl_down_sync(0xFFFFFFFFu, acc, off);
        if (lane + off < 32) acc += o;
    }
    unsigned int run = acc - tot;
    int rem = *s_rem;
    unsigned int pref = *s_prefix;
#pragma unroll
    for (int e = 7; e >= 0; --e) {
        unsigned int ge = run + b[e];
        if ((int)run < rem && (int)ge >= rem) {
            *s_prefix = pref | ((unsigned int)(base + e) << shift);
            *s_rem = rem - (int)run;
        }
        run = ge;
    }
}

// ---------------------------------------------------------------------------
// kZ: single block. PDL prologue overlaps kA; wait before consuming results.
// Fast path: rank precollected candidates (C >= k proves they contain the
// top-k). Fallback: full drill-down for any input shape.
// ---------------------------------------------------------------------------
__global__ void kZ(const float* __restrict__ scores, float* __restrict__ out,
                   const int* kptr, int n, int nSeg, int nBlkA) {
    __shared__ unsigned long long ckeys[CKEY_CAP];
    __shared__ unsigned int hist[256];
    __shared__ unsigned int s_prefix;
    __shared__ int s_rem;
    __shared__ int seglist[SEGL_CAP];
    __shared__ int sublist[SUBL_CAP];
    __shared__ int s_nseg, s_nsub, s_nc;
    int tid  = threadIdx.x;
    int lane = tid & 31;

    // ---- PDL prologue: independent of kA's output ----
    int k = kptr ? *kptr : 32;           // kptr buffer is a kernel input,
    if (k < 1) k = 1;                    // written before the graph runs
    if (k > MAXK) k = MAXK;
    hist[tid] = 0u;
    if (tid == 0) { s_prefix = 0u; s_rem = k; s_nseg = 0; s_nsub = 0; s_nc = 0; }
    __syncthreads();

    // ---- wait for kA's writes to be visible ----
    asm volatile("griddepcontrol.wait;");

    int C0 = g_cand_count;

    if (C0 >= k && C0 <= CKEY_CAP) {
        // ---- FAST PATH: candidates provably contain the top-k ----
        for (int j = tid; j < C0; j += TPB_Z) ckeys[j] = g_cand[j];
        __syncthreads();
        for (int j = tid; j < C0; j += TPB_Z) {
            unsigned long long kj = ckeys[j];
            int rank = 0;
            for (int i = 0; i < C0; ++i) rank += (ckeys[i] > kj);
            if (rank < k)
                out[0xFFFFFFFFu - (unsigned int)(kj & 0xFFFFFFFFu)] = 1.0f;
        }
        __syncthreads();
        if (tid == 0) g_cand_count = 0;      // reset for next replay
        return;
    }

    // ---- FALLBACK: full drill-down (any input shape) ----
    const unsigned int* src = (k <= nBlkA) ? g_blk_max : g_seg_max;
    int M = (k <= nBlkA) ? nBlkA : nSeg;
    if (k > M) k = M;

    for (int j = tid; j < M; j += TPB_Z) atomicAdd(&hist[src[j] >> 24], 1u);
    __syncthreads();
    if (tid < 32) radix_pick(hist, &s_prefix, &s_rem, 24, lane);
    __syncthreads();
    hist[tid] = 0u;
    unsigned int p8 = s_prefix >> 24;
    __syncthreads();
    for (int j = tid; j < M; j += TPB_Z) {
        unsigned int v = src[j];
        if ((v >> 24) == p8) atomicAdd(&hist[(v >> 16) & 255u], 1u);
    }
    __syncthreads();
    if (tid < 32) radix_pick(hist, &s_prefix, &s_rem, 16, lane);
    __syncthreads();
    unsigned int T = s_prefix;     // 16-bit floor <= true k-th max

    int nSeg4 = nSeg >> 2;
    const uint4* sm4 = (const uint4*)g_seg_max;
    for (int j = tid; j < nSeg4; j += TPB_Z) {
        uint4 v = sm4[j];
        int b = 4 * j;
        if (v.x >= T) { int p = atomicAdd(&s_nseg, 1); if (p < SEGL_CAP) seglist[p] = b;     }
        if (v.y >= T) { int p = atomicAdd(&s_nseg, 1); if (p < SEGL_CAP) seglist[p] = b + 1; }
        if (v.z >= T) { int p = atomicAdd(&s_nseg, 1); if (p < SEGL_CAP) seglist[p] = b + 2; }
        if (v.w >= T) { int p = atomicAdd(&s_nseg, 1); if (p < SEGL_CAP) seglist[p] = b + 3; }
    }
    for (int j = nSeg4 * 4 + tid; j < nSeg; j += TPB_Z) {
        if (g_seg_max[j] >= T) {
            int p = atomicAdd(&s_nseg, 1);
            if (p < SEGL_CAP) seglist[p] = j;
        }
    }
    __syncthreads();
    int F = s_nseg < SEGL_CAP ? s_nseg : SEGL_CAP;

    for (int t = tid; t < F * SUBS_PER_SEG; t += TPB_Z) {
        int sub = seglist[t >> 3] * SUBS_PER_SEG + (t & 7);
        if (g_sub_max[sub] >= T) {
            int p = atomicAdd(&s_nsub, 1);
            if (p < SUBL_CAP) sublist[p] = sub;
        }
    }
    __syncthreads();
    int F2 = s_nsub < SUBL_CAP ? s_nsub : SUBL_CAP;

    const float4* s4 = (const float4*)scores;
    int W = F2 * SUB_F4;
    for (int w = tid; w < W; w += TPB_Z) {
        int idx4 = sublist[w >> 6] * SUB_F4 + (w & 63);
        int e0   = idx4 * 4;
        if (e0 + 3 < n) {
            float4 v = s4[idx4];
            unsigned int uu[4] = {fmono(v.x), fmono(v.y), fmono(v.z), fmono(v.w)};
#pragma unroll
            for (int e = 0; e < 4; ++e) {
                if (uu[e] >= T) {
                    int p = atomicAdd(&s_nc, 1);
                    if (p < CKEY_CAP)
                        ckeys[p] = ((unsigned long long)uu[e] << 32) |
                                   (unsigned int)(0xFFFFFFFFu - (unsigned int)(e0 + e));
                }
            }
        } else {
            for (int e = 0; e < 4; ++e) {
                int i = e0 + e;
                if (i < n) {
                    unsigned int uu = fmono(scores[i]);
                    if (uu >= T) {
                        int p = atomicAdd(&s_nc, 1);
                        if (p < CKEY_CAP)
                            ckeys[p] = ((unsigned long long)uu << 32) |
                                       (unsigned int)(0xFFFFFFFFu - (unsigned int)i);
                    }
                }
            }
        }
    }
    __syncthreads();
    int C = s_nc < CKEY_CAP ? s_nc : CKEY_CAP;

    for (int j = tid; j < C; j += TPB_Z) {
        unsigned long long kj = ckeys[j];
        int rank = 0;
        for (int i = 0; i < C; ++i) rank += (ckeys[i] > kj);
        if (rank < k)
            out[0xFFFFFFFFu - (unsigned int)(kj & 0xFFFFFFFFu)] = 1.0f;
    }
    __syncthreads();
    if (tid == 0) g_cand_count = 0;          // reset for next replay
}

// ---------------------------------------------------------------------------
extern "C" void kernel_launch(void* const* d_in, const int* in_sizes, int n_in,
                              void* d_out, int out_size) {
    const float* scores = (const float*)d_in[0];
    int n = in_sizes[0];
    const int* kptr = nullptr;
    for (int i = 0; i < n_in; ++i) {
        if (in_sizes[i] == 1) {
            kptr = (const int*)d_in[i];
        } else {
            scores = (const float*)d_in[i];
            n = in_sizes[i];
        }
    }
    float* out = (float*)d_out;

    int nSeg = (n + SEG_ELEMS - 1) / SEG_ELEMS;      // 8192 for N = 16,777,216
    if (nSeg > MAX_SEGS) nSeg = MAX_SEGS;
    int nBlkA = (nSeg + WARPS_A - 1) / WARPS_A;      // 512
    if (nBlkA > MAX_BLKA) nBlkA = MAX_BLKA;

    kA<<<nBlkA, TPB_A>>>(scores, out, n, nSeg);

    // kZ with programmatic dependent launch: its prologue overlaps kA's tail.
    cudaLaunchConfig_t cfg = {};
    cfg.gridDim  = dim3(1, 1, 1);
    cfg.blockDim = dim3(TPB_Z, 1, 1);
    cfg.dynamicSmemBytes = 0;
    cfg.stream = 0;                       // legacy default stream (captured)
    cudaLaunchAttribute attr[1];
    attr[0].id = cudaLaunchAttributeProgrammaticStreamSerialization;
    attr[0].val.programmaticStreamSerializationAllowed = 1;
    cfg.attrs = attr;
    cfg.numAttrs = 1;
    cudaLaunchKernelEx(&cfg, kZ, scores, out, kptr, n, nSeg, nBlkA);
}